// round 10
// baseline (speedup 1.0000x reference)
#include <cuda_runtime.h>
#include <cuda_bf16.h>

#define Bsz 8
#define Sq  2048
#define Dd  256

__device__ unsigned short g_wh[Dd * Dd];
__device__ unsigned short g_wl[Dd * Dd];
__device__ unsigned short g_ph[(size_t)Bsz * (Sq + 1) * Dd];
__device__ unsigned short g_pl[(size_t)Bsz * (Sq + 1) * Dd];
__device__ unsigned short g_eh[(size_t)Bsz * Sq * Dd];
__device__ unsigned short g_el[(size_t)Bsz * Sq * Dd];
__device__ unsigned short g_eth[(size_t)Bsz * Dd * Sq];
__device__ unsigned short g_etl[(size_t)Bsz * Dd * Sq];
__device__ float g_pacc[768 * 64 * 256];
__device__ float g_pdn[768 * 64];

__device__ const signed char U_M[80] = {
    31,31,31,31, 30,30,30, 29,29,29, 28,28,28, 27,27,27, 26,26,26, 25,25,25,
    24,24,24, 23,23,23, 22,22, 21,21, 20,20, 19,19, 18,18, 17,17, 16,16, 15,15,
    14,13,12,11,10,9,8,7,
    30,22,14,6, 29,21,13,5, 28,20,12,4, 27,19,11,3, 26,18,10,2, 25,17,9,1, 24,16,8,0};
__device__ const signed char U_S[80] = {
    0,1,2,3, 0,1,2, 0,1,2, 0,1,2, 0,1,2, 0,1,2, 0,1,2,
    0,1,2, 0,1,2, 0,1, 0,1, 0,1, 0,1, 0,1, 0,1, 0,1, 0,1,
    0,0,0,0,0,0,0,0,
    3,2,1,0, 3,2,1,0, 3,2,1,0, 3,2,1,0, 3,2,1,0, 3,2,1,0, 3,2,1,0};

__device__ __forceinline__ unsigned pack_bf16(float a, float b) {
    __nv_bfloat162 t = __floats2bfloat162_rn(a, b);
    return *(unsigned*)&t;
}
__device__ __forceinline__ void mma16816(float* d, const unsigned* a, unsigned b0, unsigned b1) {
    asm volatile("mma.sync.aligned.m16n8k16.row.col.f32.bf16.bf16.f32 "
        "{%0,%1,%2,%3}, {%4,%5,%6,%7}, {%8,%9}, {%0,%1,%2,%3};"
        : "+f"(d[0]), "+f"(d[1]), "+f"(d[2]), "+f"(d[3])
        : "r"(a[0]), "r"(a[1]), "r"(a[2]), "r"(a[3]), "r"(b0), "r"(b1));
}
__device__ __forceinline__ void ldsm4(unsigned* r, unsigned addr) {
    asm volatile("ldmatrix.sync.aligned.m8n8.x4.shared.b16 {%0,%1,%2,%3}, [%4];"
        : "=r"(r[0]), "=r"(r[1]), "=r"(r[2]), "=r"(r[3]) : "r"(addr));
}
__device__ __forceinline__ unsigned smem_u32(const void* p) {
    unsigned a;
    asm("{ .reg .u64 t; cvta.to.shared.u64 t, %1; cvt.u32.u64 %0, t; }" : "=r"(a) : "l"(p));
    return a;
}
__device__ __forceinline__ void cpasync16(unsigned dst, const void* src) {
    asm volatile("cp.async.cg.shared.global [%0], [%1], 16;" :: "r"(dst), "l"(src));
}
#define CP_COMMIT() asm volatile("cp.async.commit_group;" ::: "memory")
#define CP_WAIT1()  asm volatile("cp.async.wait_group 1;" ::: "memory")
#define CP_WAIT0()  asm volatile("cp.async.wait_group 0;" ::: "memory")

// ---------------- kernel 1: W_eff fold -> bf16 hi/lo ----------------
__global__ void weff_kernel(const float* __restrict__ Wo) {
    int d = blockIdx.x, dp = threadIdx.x;
    float s = 0.f;
#pragma unroll
    for (int h = 0; h < 8; h++) s += Wo[(size_t)d * (Dd * 8) + h * Dd + dp];
    __nv_bfloat16 hb = __float2bfloat16(s);
    float hf = __bfloat162float(hb);
    __nv_bfloat16 lb = __float2bfloat16(s - hf);
    g_wh[d * Dd + dp] = *(unsigned short*)&hb;
    g_wl[d * Dd + dp] = *(unsigned short*)&lb;
}

// ---------------- kernel 2: fp32 -> bf16 hi/lo ----------------
__global__ void conv_kernel(const float* __restrict__ X, int sel) {
    unsigned short* Hi = sel ? g_eh : g_ph;
    unsigned short* Lo = sel ? g_el : g_pl;
    size_t i = (size_t)blockIdx.x * 256 + threadIdx.x;
    float4 v = ((const float4*)X)[i];
    float hx = __bfloat162float(__float2bfloat16(v.x));
    float hy = __bfloat162float(__float2bfloat16(v.y));
    float hz = __bfloat162float(__float2bfloat16(v.z));
    float hw = __bfloat162float(__float2bfloat16(v.w));
    ((uint2*)Hi)[i] = make_uint2(pack_bf16(hx, hy), pack_bf16(hz, hw));
    ((uint2*)Lo)[i] = make_uint2(pack_bf16(v.x - hx, v.y - hy), pack_bf16(v.z - hz, v.w - hw));
}

// ---------------- kernel 3: e2t[b][c][s] via mma ----------------
#define EWH 0
#define EWL 8192
#define EEH 16384
#define EEL 49152
#define EW_TOTAL 81920

__global__ __launch_bounds__(512, 1) void e2t_mma_kernel() {
    extern __shared__ char smem[];
    unsigned sb = smem_u32(smem);
    int tid = threadIdx.x, w = tid >> 5, lane = tid & 31;
    int g = lane >> 2, t = lane & 3;
    int cq = w >> 2, sr = w & 3;
    int bx = blockIdx.x;
    int b = bx >> 3, s_in = (bx & 7) * 256;
    int c0 = blockIdx.y * 64;

    int l7 = lane & 7;
    int asel = lane >> 4, bsel = (lane >> 3) & 1;
    int aRow = cq * 16 + (lane & 15);

    float acc[32];
#pragma unroll
    for (int i = 0; i < 32; i++) acc[i] = 0.f;

    int wr = tid >> 3, wcp = tid & 7;
    int er = tid >> 1, ehf = tid & 1;
    const unsigned short* egsrc = ehf ? g_el : g_eh;
    unsigned edst = sb + (ehf ? EEL : EEH) + er * 128;

    for (int kit = 0; kit < 4; kit++) {
        int k0 = kit * 64;
        __syncthreads();
        {
            size_t gu = ((size_t)(c0 + wr) << 5) + (k0 >> 3) + wcp;
            unsigned pc = (unsigned)(wcp ^ (wr & 7));
            cpasync16(sb + EWH + wr * 128 + pc * 16, (const uint4*)g_wh + gu);
            cpasync16(sb + EWL + wr * 128 + pc * 16, (const uint4*)g_wl + gu);
        }
        {
            size_t gu = ((size_t)(b * Sq + s_in + er) << 5) + (k0 >> 3);
#pragma unroll
            for (int j = 0; j < 8; j++) {
                unsigned pc = (unsigned)(j ^ (er & 7));
                cpasync16(edst + pc * 16, (const uint4*)egsrc + gu + j);
            }
        }
        CP_COMMIT();
        CP_WAIT0();
        __syncthreads();

#pragma unroll
        for (int ks = 0; ks < 4; ks++) {
            unsigned pca = (unsigned)((2 * ks + asel) ^ l7);
            unsigned ah[4], al[4];
            ldsm4(ah, sb + EWH + aRow * 128 + pca * 16);
            ldsm4(al, sb + EWL + aRow * 128 + pca * 16);
#pragma unroll
            for (int jn = 0; jn < 4; jn++) {
                int brow = sr * 64 + jn * 16 + ((lane >> 4) << 3) + (lane & 7);
                unsigned pcb = (unsigned)((2 * ks + bsel) ^ l7);
                unsigned bh[4], bl[4];
                ldsm4(bh, sb + EEH + brow * 128 + pcb * 16);
                ldsm4(bl, sb + EEL + brow * 128 + pcb * 16);
                mma16816(acc + jn * 8,     ah, bh[0], bh[1]);
                mma16816(acc + jn * 8 + 4, ah, bh[2], bh[3]);
                mma16816(acc + jn * 8,     ah, bl[0], bl[1]);
                mma16816(acc + jn * 8 + 4, ah, bl[2], bl[3]);
                mma16816(acc + jn * 8,     al, bh[0], bh[1]);
                mma16816(acc + jn * 8 + 4, al, bh[2], bh[3]);
            }
        }
    }

    int lr0 = cq * 16 + g, lr1 = lr0 + 8;
#pragma unroll
    for (int jn = 0; jn < 4; jn++)
#pragma unroll
        for (int h = 0; h < 2; h++) {
            int col = sr * 64 + jn * 16 + h * 8 + 2 * t;
            int s = s_in + col;
            float a0 = acc[jn * 8 + h * 4 + 0], a1 = acc[jn * 8 + h * 4 + 1];
            float a2 = acc[jn * 8 + h * 4 + 2], a3 = acc[jn * 8 + h * 4 + 3];
            float h0 = __bfloat162float(__float2bfloat16(a0));
            float h1 = __bfloat162float(__float2bfloat16(a1));
            float h2 = __bfloat162float(__float2bfloat16(a2));
            float h3 = __bfloat162float(__float2bfloat16(a3));
            size_t i0 = (((size_t)(b * Dd + c0 + lr0)) * Sq + s) >> 1;
            size_t i1 = (((size_t)(b * Dd + c0 + lr1)) * Sq + s) >> 1;
            ((unsigned*)g_eth)[i0] = pack_bf16(h0, h1);
            ((unsigned*)g_etl)[i0] = pack_bf16(a0 - h0, a1 - h1);
            ((unsigned*)g_eth)[i1] = pack_bf16(h2, h3);
            ((unsigned*)g_etl)[i1] = pack_bf16(a2 - h2, a3 - h3);
        }
}

// ---------------- kernel 4: attention (32-row half-units, 2 CTA/SM) ----------------
#define SQH 0
#define SQL 16384
#define SKH 32768
#define SKL 49152
#define SEH 65536
#define SEL 86016
#define SPH 106496
#define SPL 109056
#define SDN 111616
#define SM_TOTAL 112128
#define PSTR 20

__global__ __launch_bounds__(256, 2) void attn_mma_kernel(float* __restrict__ Out) {
    extern __shared__ char smem[];
    unsigned sb = smem_u32(smem);
    int tid = threadIdx.x, w = tid >> 5, lane = tid & 31;
    int g = lane >> 2, t = lane & 3;
    int rg = w & 1;             // row group: rows rg*16..+15 (of 32)
    int kq = w >> 1;            // MMA1 key-eighth (8 keys) / MMA2 col-quarter (64 cols)

    int bx = blockIdx.x;
    int u = bx >> 1, half = bx & 1;
    int b = u & 7, idx = u >> 3;
    int m = U_M[idx], s = U_S[idx];
    int q0 = m * 64 + half * 32;
    int k0 = s * 512;
    int kend = (m + 1) * 64;
    if (kend > k0 + 512) kend = k0 + 512;
    if (kend > q0 + 32) { if (half == 0) kend = q0 + 32; }
    bool finalTile = (m <= 7);

    // Q load (rows q0+1..q0+32), swizzled 512B rows
    {
        int r = tid >> 3;
        int cp = (tid & 7) * 4;
        const uint4* srcH = (const uint4*)g_ph + ((size_t)(b * (Sq + 1) + q0 + 1 + r)) * 32 + cp;
        const uint4* srcL = (const uint4*)g_pl + ((size_t)(b * (Sq + 1) + q0 + 1 + r)) * 32 + cp;
#pragma unroll
        for (int j = 0; j < 4; j++) {
            unsigned pc = (unsigned)((cp + j) ^ (r & 7));
            *(uint4*)(smem + SQH + r * 512 + pc * 16) = srcH[j];
            *(uint4*)(smem + SQL + r * 512 + pc * 16) = srcL[j];
        }
    }

    float acc[32];
#pragma unroll
    for (int i = 0; i < 32; i++) acc[i] = 0.f;
    float dsum0 = 0.f, dsum1 = 0.f;

    int l7 = lane & 7;
    int asel = lane >> 4;
    int aRow = rg * 16 + (lane & 15);
    unsigned qbH = sb + SQH + aRow * 512;
    unsigned qbL = sb + SQL + aRow * 512;
    unsigned kbH = sb + SKH + (kq * 8 + l7) * 512;   // MMA1 B rows (8 keys)
    unsigned kbL = sb + SKL + (kq * 8 + l7) * 512;
    int bch8 = lane >> 3;                            // chunk offset within x4 pair-load
    int erow = kq * 64 + ((lane >> 4) << 3) + l7;    // MMA2 B rows (cols)
    unsigned ebH = sb + SEH + erow * 80 + ((lane >> 3) & 1) * 16;
    unsigned ebL = sb + SEL + erow * 80 + ((lane >> 3) & 1) * 16;
    unsigned* P32h = (unsigned*)(smem + SPH);
    unsigned* P32l = (unsigned*)(smem + SPL);
    int prow0 = (rg * 16 + g) * PSTR;
    int prow1 = prow0 + 8 * PSTR;

    // cp.async assignments
    int krr = tid >> 3, kcp = (tid & 7) * 4;
    size_t kgu_base = ((size_t)(b * (Sq + 1) + krr)) * 32;
    int er = tid;
    size_t egu_base = (size_t)(b * 256 + er) * 256;
    unsigned edH = sb + SEH + er * 80;
    unsigned edL = sb + SEL + er * 80;

    auto issueK = [&](int kb) {
        size_t gu = kgu_base + (size_t)kb * 32;
#pragma unroll
        for (int j = 0; j < 4; j++) {
            int c4 = kcp + j;
            unsigned pc = (unsigned)(c4 ^ (krr & 7));
            cpasync16(sb + SKH + krr * 512 + pc * 16, (const uint4*)g_ph + gu + c4);
            cpasync16(sb + SKL + krr * 512 + pc * 16, (const uint4*)g_pl + gu + c4);
        }
        CP_COMMIT();
    };
    auto issueE = [&](int kb) {
        size_t gu = egu_base + (kb >> 3);
#pragma unroll
        for (int j = 0; j < 4; j++) {
            cpasync16(edH + j * 16, (const uint4*)g_eth + gu + j);
            cpasync16(edL + j * 16, (const uint4*)g_etl + gu + j);
        }
        CP_COMMIT();
    };

    issueK(k0);
    issueE(k0);

    for (int kb = k0; kb < kend; kb += 32) {
        bool more = (kb + 32 < kend);
        CP_WAIT1();                 // K(kb) arrived
        __syncthreads();

        // ---- MMA1: S[16 rows x 8 keys]
        float S[4] = {0.f, 0.f, 0.f, 0.f};
#pragma unroll
        for (int j = 0; j < 8; j++) {           // two k16-steps per j
            unsigned achA = (unsigned)(((4 * j + asel) ^ l7) << 4);
            unsigned achB = (unsigned)(((4 * j + 2 + asel) ^ l7) << 4);
            unsigned bch  = (unsigned)(((4 * j + bch8) ^ l7) << 4);
            unsigned ahA[4], ahB[4], alA[4], alB[4], bh[4], bl[4];
            ldsm4(ahA, qbH + achA);
            ldsm4(ahB, qbH + achB);
            ldsm4(bh, kbH + bch);
            ldsm4(alA, qbL + achA);
            ldsm4(alB, qbL + achB);
            ldsm4(bl, kbL + bch);
            mma16816(S, ahA, bh[0], bh[1]);
            mma16816(S, ahB, bh[2], bh[3]);
            mma16816(S, ahA, bl[0], bl[1]);
            mma16816(S, ahB, bl[2], bl[3]);
            mma16816(S, alA, bh[0], bh[1]);
            mma16816(S, alB, bh[2], bh[3]);
        }
        __syncthreads();            // done reading K
        if (more) issueK(kb + 32);

        // ---- exp epilogue -> P smem
        {
            int r0 = q0 + rg * 16 + g, r1 = r0 + 8;
            int kc = kb + kq * 8 + 2 * t;
            float v0 = fminf(fmaxf(S[0] * 0.0625f, -10.f), 10.f);
            float v1 = fminf(fmaxf(S[1] * 0.0625f, -10.f), 10.f);
            float v2 = fminf(fmaxf(S[2] * 0.0625f, -10.f), 10.f);
            float v3 = fminf(fmaxf(S[3] * 0.0625f, -10.f), 10.f);
            float p0 = (kc     <= r0) ? __expf(v0) : 0.f;
            float p1 = (kc + 1 <= r0) ? __expf(v1) : 0.f;
            float p2 = (kc     <= r1) ? __expf(v2) : 0.f;
            float p3 = (kc + 1 <= r1) ? __expf(v3) : 0.f;
            dsum0 += p0 + p1;
            dsum1 += p2 + p3;
            float h0 = __bfloat162float(__float2bfloat16(p0));
            float h1 = __bfloat162float(__float2bfloat16(p1));
            float h2 = __bfloat162float(__float2bfloat16(p2));
            float h3 = __bfloat162float(__float2bfloat16(p3));
            int c32 = kq * 4 + t;
            P32h[prow0 + c32] = pack_bf16(h0, h1);
            P32h[prow1 + c32] = pack_bf16(h2, h3);
            P32l[prow0 + c32] = pack_bf16(p0 - h0, p1 - h1);
            P32l[prow1 + c32] = pack_bf16(p2 - h2, p3 - h3);
        }
        if (more) CP_WAIT1(); else CP_WAIT0();   // E(kb) arrived
        __syncthreads();            // E + P visible

        // ---- MMA2: acc[16 rows x 64 cols] += P[16x32] . E
#pragma unroll
        for (int ks = 0; ks < 2; ks++) {
            unsigned ph[4], pl[4];
            ph[0] = P32h[prow0 + ks * 8 + t];
            ph[1] = P32h[prow1 + ks * 8 + t];
            ph[2] = P32h[prow0 + ks * 8 + 4 + t];
            ph[3] = P32h[prow1 + ks * 8 + 4 + t];
            pl[0] = P32l[prow0 + ks * 8 + t];
            pl[1] = P32l[prow1 + ks * 8 + t];
            pl[2] = P32l[prow0 + ks * 8 + 4 + t];
            pl[3] = P32l[prow1 + ks * 8 + 4 + t];
#pragma unroll
            for (int jp = 0; jp < 4; jp++) {
                unsigned eo = (unsigned)(jp * 1280 + ks * 32);
                unsigned eh[4], el[4];
                ldsm4(eh, ebH + eo);
                ldsm4(el, ebL + eo);
                mma16816(acc + jp * 8,     ph, eh[0], eh[1]);
                mma16816(acc + jp * 8 + 4, ph, eh[2], eh[3]);
                mma16816(acc + jp * 8,     pl, eh[0], eh[1]);
                mma16816(acc + jp * 8 + 4, pl, eh[2], eh[3]);
                mma16816(acc + jp * 8,     ph, el[0], el[1]);
                mma16816(acc + jp * 8 + 4, ph, el[2], el[3]);
            }
        }
        __syncthreads();            // done reading E
        if (more) issueE(kb + 32);
    }

    // denominators: quad reduce, sum over 4 key-groups
    dsum0 += __shfl_xor_sync(0xFFFFFFFF, dsum0, 1);
    dsum0 += __shfl_xor_sync(0xFFFFFFFF, dsum0, 2);
    dsum1 += __shfl_xor_sync(0xFFFFFFFF, dsum1, 1);
    dsum1 += __shfl_xor_sync(0xFFFFFFFF, dsum1, 2);
    float* Dn = (float*)(smem + SDN);
    if (t == 0) {
        Dn[kq * 32 + rg * 16 + g] = dsum0;
        Dn[kq * 32 + rg * 16 + g + 8] = dsum1;
    }
    __syncthreads();

    int lr0 = rg * 16 + g, lr1 = lr0 + 8;
    float d0 = Dn[lr0] + Dn[32 + lr0] + Dn[64 + lr0] + Dn[96 + lr0];
    float d1 = Dn[lr1] + Dn[32 + lr1] + Dn[64 + lr1] + Dn[96 + lr1];

    if (finalTile) {
        int r0 = q0 + lr0, r1 = q0 + lr1;
        float inv0 = 1.f / ((float)(r0 + 1) * d0);
        float inv1 = 1.f / ((float)(r1 + 1) * d1);
        float* o0 = Out + ((size_t)(b * Sq + r0)) * 256;
        float* o1 = Out + ((size_t)(b * Sq + r1)) * 256;
#pragma unroll
        for (int jp = 0; jp < 4; jp++)
#pragma unroll
            for (int nt = 0; nt < 2; nt++) {
                int col = kq * 64 + jp * 16 + nt * 8 + 2 * t;
                *(float2*)(o0 + col) = make_float2(acc[jp * 8 + nt * 4 + 0] * inv0,
                                                   acc[jp * 8 + nt * 4 + 1] * inv0);
                *(float2*)(o1 + col) = make_float2(acc[jp * 8 + nt * 4 + 2] * inv1,
                                                   acc[jp * 8 + nt * 4 + 3] * inv1);
            }
    } else {
        int slot = (b * 24 + (m - 8)) * 4 + s;
        float* pa = g_pacc + (size_t)slot * 16384;
        int pr0 = half * 32 + lr0, pr1 = half * 32 + lr1;
        if (t == 0 && kq == 0) {
            g_pdn[slot * 64 + pr0] = d0;
            g_pdn[slot * 64 + pr1] = d1;
        }
#pragma unroll
        for (int jp = 0; jp < 4; jp++)
#pragma unroll
            for (int nt = 0; nt < 2; nt++) {
                int col = kq * 64 + jp * 16 + nt * 8 + 2 * t;
                *(float2*)(pa + pr0 * 256 + col) = make_float2(acc[jp * 8 + nt * 4 + 0],
                                                               acc[jp * 8 + nt * 4 + 1]);
                *(float2*)(pa + pr1 * 256 + col) = make_float2(acc[jp * 8 + nt * 4 + 2],
                                                               acc[jp * 8 + nt * 4 + 3]);
            }
    }
}

// ---------------- kernel 5: reduce split-k partials ----------------
__global__ void reduce_kernel(float* __restrict__ Out) {
    __shared__ float dns[64];
    int tile = blockIdx.x;
    int b = tile / 24, m = (tile % 24) + 8;
    int cnt = (m + 8) >> 3;
    int slot0 = (b * 24 + (m - 8)) * 4;
    int tid = threadIdx.x;
    if (tid < 64) {
        float d = 0.f;
        for (int s = 0; s < cnt; s++) d += g_pdn[(slot0 + s) * 64 + tid];
        dns[tid] = d;
    }
    __syncthreads();
    int q0 = m * 64;
    for (int i = tid; i < 16384; i += 256) {
        int r = i >> 8, c = i & 255;
        float a = 0.f;
        for (int s = 0; s < cnt; s++) a += g_pacc[(size_t)(slot0 + s) * 16384 + i];
        int q = q0 + r;
        Out[((size_t)(b * Sq + q)) * 256 + c] = a / ((float)(q + 1) * dns[r]);
    }
}

// ---------------------------------------------------------------------------
extern "C" void kernel_launch(void* const* d_in, const int* in_sizes, int n_in,
                              void* d_out, int out_size) {
    const float* e  = (const float*)d_in[0];
    const float* p  = (const float*)d_in[1];
    const float* Wo = (const float*)d_in[2];
    float* out = (float*)d_out;

    cudaFuncSetAttribute(attn_mma_kernel, cudaFuncAttributeMaxDynamicSharedMemorySize, SM_TOTAL);
    cudaFuncSetAttribute(e2t_mma_kernel, cudaFuncAttributeMaxDynamicSharedMemorySize, EW_TOTAL);

    weff_kernel<<<Dd, Dd>>>(Wo);
    conv_kernel<<<(Bsz * (Sq + 1) * Dd) / 1024, 256>>>(p, 0);
    conv_kernel<<<(Bsz * Sq * Dd) / 1024, 256>>>(e, 1);
    e2t_mma_kernel<<<dim3(64, 4), 512, EW_TOTAL>>>();
    attn_mma_kernel<<<1280, 256, SM_TOTAL>>>(out);
    reduce_kernel<<<192, 256>>>(out);
}

// round 13
// speedup vs baseline: 1.1476x; 1.1476x over previous
#include <cuda_runtime.h>
#include <cuda_bf16.h>

#define Bsz 8
#define Sq  2048
#define Dd  256

__device__ unsigned short g_wh[Dd * Dd];
__device__ unsigned short g_wl[Dd * Dd];
__device__ unsigned short g_eh[(size_t)Bsz * Sq * Dd];
__device__ unsigned short g_el[(size_t)Bsz * Sq * Dd];
__device__ float g_ptf[(size_t)Bsz * (Sq + 1) * Dd];   // tf32-rounded p
__device__ float g_et[(size_t)Bsz * Dd * Sq];          // tf32-rounded e2t [b][c][s]
__device__ float g_pacc[768 * 64 * 256];
__device__ float g_pdn[768 * 64];

__device__ const signed char U_M[80] = {
    31,31,31,31, 30,30,30, 29,29,29, 28,28,28, 27,27,27, 26,26,26, 25,25,25,
    24,24,24, 23,23,23, 22,22, 21,21, 20,20, 19,19, 18,18, 17,17, 16,16, 15,15,
    14,13,12,11,10,9,8,7,
    30,22,14,6, 29,21,13,5, 28,20,12,4, 27,19,11,3, 26,18,10,2, 25,17,9,1, 24,16,8,0};
__device__ const signed char U_S[80] = {
    0,1,2,3, 0,1,2, 0,1,2, 0,1,2, 0,1,2, 0,1,2, 0,1,2,
    0,1,2, 0,1,2, 0,1, 0,1, 0,1, 0,1, 0,1, 0,1, 0,1, 0,1,
    0,0,0,0,0,0,0,0,
    3,2,1,0, 3,2,1,0, 3,2,1,0, 3,2,1,0, 3,2,1,0, 3,2,1,0, 3,2,1,0};

__device__ __forceinline__ unsigned pack_bf16(float a, float b) {
    __nv_bfloat162 t = __floats2bfloat162_rn(a, b);
    return *(unsigned*)&t;
}
__device__ __forceinline__ float tf32r(float x) {
    unsigned u;
    asm("cvt.rna.tf32.f32 %0, %1;" : "=r"(u) : "f"(x));
    return __uint_as_float(u);
}
__device__ __forceinline__ void mma16816(float* d, const unsigned* a, unsigned b0, unsigned b1) {
    asm volatile("mma.sync.aligned.m16n8k16.row.col.f32.bf16.bf16.f32 "
        "{%0,%1,%2,%3}, {%4,%5,%6,%7}, {%8,%9}, {%0,%1,%2,%3};"
        : "+f"(d[0]), "+f"(d[1]), "+f"(d[2]), "+f"(d[3])
        : "r"(a[0]), "r"(a[1]), "r"(a[2]), "r"(a[3]), "r"(b0), "r"(b1));
}
__device__ __forceinline__ void mmatf32(float* d, const unsigned* a, unsigned b0, unsigned b1) {
    asm volatile("mma.sync.aligned.m16n8k8.row.col.f32.tf32.tf32.f32 "
        "{%0,%1,%2,%3}, {%4,%5,%6,%7}, {%8,%9}, {%0,%1,%2,%3};"
        : "+f"(d[0]), "+f"(d[1]), "+f"(d[2]), "+f"(d[3])
        : "r"(a[0]), "r"(a[1]), "r"(a[2]), "r"(a[3]), "r"(b0), "r"(b1));
}
__device__ __forceinline__ void ldsm4(unsigned* r, unsigned addr) {
    asm volatile("ldmatrix.sync.aligned.m8n8.x4.shared.b16 {%0,%1,%2,%3}, [%4];"
        : "=r"(r[0]), "=r"(r[1]), "=r"(r[2]), "=r"(r[3]) : "r"(addr));
}
__device__ __forceinline__ unsigned smem_u32(const void* p) {
    unsigned a;
    asm("{ .reg .u64 t; cvta.to.shared.u64 t, %1; cvt.u32.u64 %0, t; }" : "=r"(a) : "l"(p));
    return a;
}
__device__ __forceinline__ void cpasync16(unsigned dst, const void* src) {
    asm volatile("cp.async.cg.shared.global [%0], [%1], 16;" :: "r"(dst), "l"(src));
}
#define CP_COMMIT() asm volatile("cp.async.commit_group;" ::: "memory")
#define CP_WAIT1()  asm volatile("cp.async.wait_group 1;" ::: "memory")
#define CP_WAIT0()  asm volatile("cp.async.wait_group 0;" ::: "memory")

// ---------------- kernel 1: W_eff fold -> bf16 hi/lo ----------------
__global__ void weff_kernel(const float* __restrict__ Wo) {
    int d = blockIdx.x, dp = threadIdx.x;
    float s = 0.f;
#pragma unroll
    for (int h = 0; h < 8; h++) s += Wo[(size_t)d * (Dd * 8) + h * Dd + dp];
    __nv_bfloat16 hb = __float2bfloat16(s);
    float hf = __bfloat162float(hb);
    __nv_bfloat16 lb = __float2bfloat16(s - hf);
    g_wh[d * Dd + dp] = *(unsigned short*)&hb;
    g_wl[d * Dd + dp] = *(unsigned short*)&lb;
}

// ---------------- kernel 2a: e -> bf16 hi/lo (e2t input) ----------------
__global__ void conv_kernel(const float* __restrict__ X) {
    size_t i = (size_t)blockIdx.x * 256 + threadIdx.x;
    float4 v = ((const float4*)X)[i];
    float hx = __bfloat162float(__float2bfloat16(v.x));
    float hy = __bfloat162float(__float2bfloat16(v.y));
    float hz = __bfloat162float(__float2bfloat16(v.z));
    float hw = __bfloat162float(__float2bfloat16(v.w));
    ((uint2*)g_eh)[i] = make_uint2(pack_bf16(hx, hy), pack_bf16(hz, hw));
    ((uint2*)g_el)[i] = make_uint2(pack_bf16(v.x - hx, v.y - hy), pack_bf16(v.z - hz, v.w - hw));
}

// ---------------- kernel 2b: p -> tf32-rounded fp32 ----------------
__global__ void tfconv_kernel(const float* __restrict__ P) {
    size_t i = (size_t)blockIdx.x * 256 + threadIdx.x;
    float4 v = ((const float4*)P)[i];
    v.x = tf32r(v.x); v.y = tf32r(v.y); v.z = tf32r(v.z); v.w = tf32r(v.w);
    ((float4*)g_ptf)[i] = v;
}

// ---------------- kernel 3: e2t[b][c][s] via bf16 3-pass mma, tf32 output ----------------
#define EWH 0
#define EWL 8192
#define EEH 16384
#define EEL 49152
#define EW_TOTAL 81920

__global__ __launch_bounds__(512, 1) void e2t_mma_kernel() {
    extern __shared__ char smem[];
    unsigned sb = smem_u32(smem);
    int tid = threadIdx.x, w = tid >> 5, lane = tid & 31;
    int g = lane >> 2, t = lane & 3;
    int cq = w >> 2, sr = w & 3;
    int bx = blockIdx.x;
    int b = bx >> 3, s_in = (bx & 7) * 256;
    int c0 = blockIdx.y * 64;

    int l7 = lane & 7;
    int asel = lane >> 4, bsel = (lane >> 3) & 1;
    int aRow = cq * 16 + (lane & 15);

    float acc[32];
#pragma unroll
    for (int i = 0; i < 32; i++) acc[i] = 0.f;

    int wr = tid >> 3, wcp = tid & 7;
    int er = tid >> 1, ehf = tid & 1;
    const unsigned short* egsrc = ehf ? g_el : g_eh;
    unsigned edst = sb + (ehf ? EEL : EEH) + er * 128;

    for (int kit = 0; kit < 4; kit++) {
        int k0 = kit * 64;
        __syncthreads();
        {
            size_t gu = ((size_t)(c0 + wr) << 5) + (k0 >> 3) + wcp;
            unsigned pc = (unsigned)(wcp ^ (wr & 7));
            cpasync16(sb + EWH + wr * 128 + pc * 16, (const uint4*)g_wh + gu);
            cpasync16(sb + EWL + wr * 128 + pc * 16, (const uint4*)g_wl + gu);
        }
        {
            size_t gu = ((size_t)(b * Sq + s_in + er) << 5) + (k0 >> 3);
#pragma unroll
            for (int j = 0; j < 8; j++) {
                unsigned pc = (unsigned)(j ^ (er & 7));
                cpasync16(edst + pc * 16, (const uint4*)egsrc + gu + j);
            }
        }
        CP_COMMIT();
        CP_WAIT0();
        __syncthreads();

#pragma unroll
        for (int ks = 0; ks < 4; ks++) {
            unsigned pca = (unsigned)((2 * ks + asel) ^ l7);
            unsigned ah[4], al[4];
            ldsm4(ah, sb + EWH + aRow * 128 + pca * 16);
            ldsm4(al, sb + EWL + aRow * 128 + pca * 16);
#pragma unroll
            for (int jn = 0; jn < 4; jn++) {
                int brow = sr * 64 + jn * 16 + ((lane >> 4) << 3) + (lane & 7);
                unsigned pcb = (unsigned)((2 * ks + bsel) ^ l7);
                unsigned bh[4], bl[4];
                ldsm4(bh, sb + EEH + brow * 128 + pcb * 16);
                ldsm4(bl, sb + EEL + brow * 128 + pcb * 16);
                mma16816(acc + jn * 8,     ah, bh[0], bh[1]);
                mma16816(acc + jn * 8 + 4, ah, bh[2], bh[3]);
                mma16816(acc + jn * 8,     ah, bl[0], bl[1]);
                mma16816(acc + jn * 8 + 4, ah, bl[2], bl[3]);
                mma16816(acc + jn * 8,     al, bh[0], bh[1]);
                mma16816(acc + jn * 8 + 4, al, bh[2], bh[3]);
            }
        }
    }

    int lr0 = cq * 16 + g, lr1 = lr0 + 8;
#pragma unroll
    for (int jn = 0; jn < 4; jn++)
#pragma unroll
        for (int h = 0; h < 2; h++) {
            int col = sr * 64 + jn * 16 + h * 8 + 2 * t;
            int s = s_in + col;
            size_t i0 = ((size_t)(b * Dd + c0 + lr0)) * Sq + s;
            size_t i1 = ((size_t)(b * Dd + c0 + lr1)) * Sq + s;
            ((float2*)g_et)[i0 >> 1] = make_float2(tf32r(acc[jn * 8 + h * 4 + 0]),
                                                   tf32r(acc[jn * 8 + h * 4 + 1]));
            ((float2*)g_et)[i1 >> 1] = make_float2(tf32r(acc[jn * 8 + h * 4 + 2]),
                                                   tf32r(acc[jn * 8 + h * 4 + 3]));
        }
}

// ---------------- kernel 4: attention (tf32 single-pass) ----------------
// smem map (bytes), all regions end-audited:
//   Q  [64 rows][1024B swz]        0 .. 65536
//   K  [64 rows][1024B swz]    65536 .. 131072
//   E  [256 rows][272B]       131072 .. 200704   (272 = 256 data + 16 pad)
//   P  [64 rows][272B]        200704 .. 218112   (68-float stride, 64 used)
//   Dn [256 floats]           218112 .. 219136
#define SQ 0
#define SK 65536
#define SE 131072
#define SP 200704
#define SDN 218112
#define SM_TOTAL 219136

__global__ __launch_bounds__(512, 1) void attn_mma_kernel(float* __restrict__ Out) {
    extern __shared__ char smem[];
    unsigned sb = smem_u32(smem);
    int tid = threadIdx.x, w = tid >> 5, lane = tid & 31;
    int g = lane >> 2, t = lane & 3;
    int quad = w >> 2;
    int role = w & 3;

    int u = blockIdx.x;
    int b = u & 7, idx = u >> 3;
    int m = U_M[idx], s = U_S[idx];
    int q0 = m * 64;
    int k0 = s * 512;
    int kend = (m + 1) * 64;
    if (kend > k0 + 512) kend = k0 + 512;
    bool finalTile = (m <= 7);

    // Q load (rows q0+1..q0+64), tf32 fp32, swizzled 1024B rows
    {
        int r = tid >> 3;
        int cp8 = (tid & 7) * 8;
        const float* src = g_ptf + ((size_t)(b * (Sq + 1) + q0 + 1 + r)) * 256;
#pragma unroll
        for (int j = 0; j < 8; j++) {
            int ch = cp8 + j;
            unsigned pc = (unsigned)(ch ^ (r & 7));
            *(float4*)(smem + SQ + r * 1024 + pc * 16) = *(const float4*)(src + ch * 4);
        }
    }

    float acc[32];
#pragma unroll
    for (int i = 0; i < 32; i++) acc[i] = 0.f;
    float dsum0 = 0.f, dsum1 = 0.f;

    // fragment lane->address precompute (tf32 frag maps, see analysis)
    int rA = quad * 16 + ((lane >> 3) & 1) * 8 + (lane & 7);
    unsigned qA = sb + SQ + rA * 1024;
    unsigned qa_r7 = (unsigned)(rA & 7);
    int chA = lane >> 4;
    int rB = ((lane >> 4) << 3) + (lane & 7);
    unsigned kB = sb + SK + (role * 16 + rB) * 1024;
    unsigned kb_r7 = (unsigned)((role * 16 + rB) & 7);
    int chB = (lane >> 3) & 1;
    unsigned pA = sb + SP + rA * 272;
    unsigned eB = sb + SE + (role * 64 + rB) * 272;
    float* Pf = (float*)(smem + SP);
    int prow0 = (quad * 16 + g) * 68;
    int prow1 = prow0 + 8 * 68;

    // cp.async assignments
    int krr = tid >> 3, kcp8 = (tid & 7) * 8;
    int er = tid >> 1, ehf = tid & 1;
    unsigned edst = sb + SE + er * 272 + ehf * 128;

    auto issueK = [&](int kb) {
        const float* src = g_ptf + ((size_t)(b * (Sq + 1) + kb + krr)) * 256;
#pragma unroll
        for (int j = 0; j < 8; j++) {
            int ch = kcp8 + j;
            unsigned pc = (unsigned)(ch ^ (krr & 7));
            cpasync16(sb + SK + krr * 1024 + pc * 16, src + ch * 4);
        }
        CP_COMMIT();
    };
    auto issueE = [&](int kb) {
        const float* src = g_et + ((size_t)(b * 256 + er)) * 2048 + kb + ehf * 32;
#pragma unroll
        for (int j = 0; j < 8; j++)
            cpasync16(edst + j * 16, src + j * 4);
        CP_COMMIT();
    };

    issueK(k0);
    issueE(k0);

    for (int kb = k0; kb < kend; kb += 64) {
        bool more = (kb + 64 < kend);
        CP_WAIT1();                 // K(kb) arrived
        __syncthreads();

        // ---- MMA1 (tf32): S[16 rows x 16 keys] per warp
        float S[8];
#pragma unroll
        for (int i = 0; i < 8; i++) S[i] = 0.f;
#pragma unroll 8
        for (int ks = 0; ks < 32; ks++) {
            unsigned a[4], bq[4];
            ldsm4(a,  qA + (((unsigned)(2 * ks + chA) ^ qa_r7) << 4));
            ldsm4(bq, kB + (((unsigned)(2 * ks + chB) ^ kb_r7) << 4));
            mmatf32(S,     a, bq[0], bq[1]);
            mmatf32(S + 4, a, bq[2], bq[3]);
        }
        __syncthreads();            // done reading K
        if (more) issueK(kb + 64);

        // ---- exp epilogue -> P smem (tf32 fp32)
        int r0 = q0 + quad * 16 + g, r1 = r0 + 8;
#pragma unroll
        for (int j = 0; j < 2; j++) {
            int c0c = kb + role * 16 + j * 8 + 2 * t;
            float v0 = fminf(fmaxf(S[j * 4 + 0] * 0.0625f, -10.f), 10.f);
            float v1 = fminf(fmaxf(S[j * 4 + 1] * 0.0625f, -10.f), 10.f);
            float v2 = fminf(fmaxf(S[j * 4 + 2] * 0.0625f, -10.f), 10.f);
            float v3 = fminf(fmaxf(S[j * 4 + 3] * 0.0625f, -10.f), 10.f);
            float p0 = (c0c     <= r0) ? __expf(v0) : 0.f;
            float p1 = (c0c + 1 <= r0) ? __expf(v1) : 0.f;
            float p2 = (c0c     <= r1) ? __expf(v2) : 0.f;
            float p3 = (c0c + 1 <= r1) ? __expf(v3) : 0.f;
            dsum0 += p0 + p1;
            dsum1 += p2 + p3;
            int cc = role * 16 + j * 8 + 2 * t;
            *(float2*)(Pf + prow0 + cc) = make_float2(tf32r(p0), tf32r(p1));
            *(float2*)(Pf + prow1 + cc) = make_float2(tf32r(p2), tf32r(p3));
        }
        if (more) CP_WAIT1(); else CP_WAIT0();   // E(kb) arrived
        __syncthreads();            // E + P visible

        // ---- MMA2 (tf32): acc[16 x 64 cols] += P[16x64] . E
#pragma unroll
        for (int ks = 0; ks < 8; ks++) {
            unsigned pa[4];
            ldsm4(pa, pA + (unsigned)(2 * ks + chA) * 16);
#pragma unroll
            for (int jp = 0; jp < 4; jp++) {
                unsigned eb[4];
                ldsm4(eb, eB + (unsigned)(jp * 16 * 272) + (unsigned)(2 * ks + chB) * 16);
                mmatf32(acc + jp * 8,     pa, eb[0], eb[1]);
                mmatf32(acc + jp * 8 + 4, pa, eb[2], eb[3]);
            }
        }
        __syncthreads();            // done reading E + P
        if (more) issueE(kb + 64);
    }

    // denominators
    dsum0 += __shfl_xor_sync(0xFFFFFFFF, dsum0, 1);
    dsum0 += __shfl_xor_sync(0xFFFFFFFF, dsum0, 2);
    dsum1 += __shfl_xor_sync(0xFFFFFFFF, dsum1, 1);
    dsum1 += __shfl_xor_sync(0xFFFFFFFF, dsum1, 2);
    float* Dn = (float*)(smem + SDN);
    if (t == 0) {
        Dn[role * 64 + quad * 16 + g] = dsum0;
        Dn[role * 64 + quad * 16 + g + 8] = dsum1;
    }
    __syncthreads();

    int lr0 = quad * 16 + g, lr1 = lr0 + 8;
    float d0 = Dn[lr0] + Dn[64 + lr0] + Dn[128 + lr0] + Dn[192 + lr0];
    float d1 = Dn[lr1] + Dn[64 + lr1] + Dn[128 + lr1] + Dn[192 + lr1];

    if (finalTile) {
        int r0 = q0 + lr0, r1 = q0 + lr1;
        float inv0 = 1.f / ((float)(r0 + 1) * d0);
        float inv1 = 1.f / ((float)(r1 + 1) * d1);
        float* o0 = Out + ((size_t)(b * Sq + r0)) * 256;
        float* o1 = Out + ((size_t)(b * Sq + r1)) * 256;
#pragma unroll
        for (int jp = 0; jp < 4; jp++)
#pragma unroll
            for (int nt = 0; nt < 2; nt++) {
                int col = role * 64 + jp * 16 + nt * 8 + 2 * t;
                *(float2*)(o0 + col) = make_float2(acc[jp * 8 + nt * 4 + 0] * inv0,
                                                   acc[jp * 8 + nt * 4 + 1] * inv0);
                *(float2*)(o1 + col) = make_float2(acc[jp * 8 + nt * 4 + 2] * inv1,
                                                   acc[jp * 8 + nt * 4 + 3] * inv1);
            }
    } else {
        int slot = (b * 24 + (m - 8)) * 4 + s;
        float* pa = g_pacc + (size_t)slot * 16384;
        if (t == 0 && role == 0) {
            g_pdn[slot * 64 + lr0] = d0;
            g_pdn[slot * 64 + lr1] = d1;
        }
#pragma unroll
        for (int jp = 0; jp < 4; jp++)
#pragma unroll
            for (int nt = 0; nt < 2; nt++) {
                int col = role * 64 + jp * 16 + nt * 8 + 2 * t;
                *(float2*)(pa + lr0 * 256 + col) = make_float2(acc[jp * 8 + nt * 4 + 0],
                                                               acc[jp * 8 + nt * 4 + 1]);
                *(float2*)(pa + lr1 * 256 + col) = make_float2(acc[jp * 8 + nt * 4 + 2],
                                                               acc[jp * 8 + nt * 4 + 3]);
            }
    }
}

// ---------------- kernel 5: reduce split-k partials ----------------
__global__ void reduce_kernel(float* __restrict__ Out) {
    __shared__ float dns[64];
    int tile = blockIdx.x;
    int b = tile / 24, m = (tile % 24) + 8;
    int cnt = (m + 8) >> 3;
    int slot0 = (b * 24 + (m - 8)) * 4;
    int tid = threadIdx.x;
    if (tid < 64) {
        float d = 0.f;
        for (int s = 0; s < cnt; s++) d += g_pdn[(slot0 + s) * 64 + tid];
        dns[tid] = d;
    }
    __syncthreads();
    int q0 = m * 64;
    for (int i = tid; i < 16384; i += 256) {
        int r = i >> 8, c = i & 255;
        float a = 0.f;
        for (int s = 0; s < cnt; s++) a += g_pacc[(size_t)(slot0 + s) * 16384 + i];
        int q = q0 + r;
        Out[((size_t)(b * Sq + q)) * 256 + c] = a / ((float)(q + 1) * dns[r]);
    }
}

// ---------------------------------------------------------------------------
extern "C" void kernel_launch(void* const* d_in, const int* in_sizes, int n_in,
                              void* d_out, int out_size) {
    const float* e  = (const float*)d_in[0];
    const float* p  = (const float*)d_in[1];
    const float* Wo = (const float*)d_in[2];
    float* out = (float*)d_out;

    cudaFuncSetAttribute(attn_mma_kernel, cudaFuncAttributeMaxDynamicSharedMemorySize, SM_TOTAL);
    cudaFuncSetAttribute(e2t_mma_kernel, cudaFuncAttributeMaxDynamicSharedMemorySize, EW_TOTAL);

    weff_kernel<<<Dd, Dd>>>(Wo);
    conv_kernel<<<(Bsz * Sq * Dd) / 1024, 256>>>(e);
    tfconv_kernel<<<(Bsz * (Sq + 1) * Dd) / 1024, 256>>>(p);
    e2t_mma_kernel<<<dim3(64, 4), 512, EW_TOTAL>>>();
    attn_mma_kernel<<<640, 512, SM_TOTAL>>>(out);
    reduce_kernel<<<192, 256>>>(out);
}